// round 9
// baseline (speedup 1.0000x reference)
#include <cuda_runtime.h>
#include <cuda_fp16.h>
#include <cuda_bf16.h>
#include <cstdint>

#define CH   256
#define HH   96
#define WW   96
#define BB   4
#define PP   (HH*WW)        // 9216
#define GG   9
#define NGB  (GG*BB)        // 36

// bf16 smem tiles: A 128 rows x 40 halves (80B stride), B 32 rows x 136 halves (272B)
#define ASTRIDE_B 80
#define BSTRIDE_B 272
#define B_OFF     10240u                 // A stage bytes = 128*80
#define STAGE     18944u                 // + B 32*272 = 8704
#define SSQ_OFF   (2*STAGE)              // 37888
#define SMEM_BYTES (SSQ_OFF + 512)       // 38400

#define GEMM_PER_B   1296                // 9 g * 2 halves * 72 ptiles
#define N_GEMM       (GEMM_PER_B*BB)     // 5184
#define EPI_PER_B    288                 // 8 ch-blocks * 36 p-blocks
#define N_EPI        (EPI_PER_B*BB)      // 1152
#define N_CTA        (N_GEMM + N_EPI)    // 6336

__device__ __nv_bfloat16 g_cenh[(size_t)BB * CH * PP];
__device__ __nv_bfloat16 g_w3h[(size_t)GG * CH * CH];
__device__ __half g_Zh[(size_t)NGB * CH * PP];   // Z[gb][c][p] fp16
__device__ float  g_ssq2[2][NGB * PP];           // per-m-half partial sumsq
__device__ int    g_done[BB];                    // gemm-tiles-completed per batch

__constant__ int c_dy[8] = {-1, -1, -1, 0, 1, 1, 1, 0};
__constant__ int c_dx[8] = {-1,  0,  1, 1, 1, 0, -1, -1};

__device__ __forceinline__ uint32_t smem_u32(const void* p) {
    uint32_t a;
    asm("{ .reg .u64 t; cvta.to.shared.u64 t, %1; cvt.u32.u64 %0, t; }" : "=r"(a) : "l"(p));
    return a;
}
#define CPA16(dst, src) asm volatile("cp.async.cg.shared.global [%0], [%1], 16;" :: "r"(dst), "l"(src) : "memory")
#define CPA_COMMIT()    asm volatile("cp.async.commit_group;" ::: "memory")
#define CPA_WAIT1()     asm volatile("cp.async.wait_group 1;" ::: "memory")
#define CPA_WAIT0()     asm volatile("cp.async.wait_group 0;" ::: "memory")

#define LDSM_X4(r, a) \
    asm volatile("ldmatrix.sync.aligned.m8n8.x4.shared.b16 {%0,%1,%2,%3}, [%4];" \
        : "=r"((r)[0]), "=r"((r)[1]), "=r"((r)[2]), "=r"((r)[3]) : "r"(a))
#define LDSM_X4T(r, a) \
    asm volatile("ldmatrix.sync.aligned.m8n8.x4.trans.shared.b16 {%0,%1,%2,%3}, [%4];" \
        : "=r"((r)[0]), "=r"((r)[1]), "=r"((r)[2]), "=r"((r)[3]) : "r"(a))

__device__ __forceinline__ void mma16(float* d, const uint32_t* a, const uint32_t* b) {
    asm volatile(
        "mma.sync.aligned.m16n8k16.row.col.f32.bf16.bf16.f32 "
        "{%0,%1,%2,%3},{%4,%5,%6,%7},{%8,%9},{%0,%1,%2,%3};"
        : "+f"(d[0]), "+f"(d[1]), "+f"(d[2]), "+f"(d[3])
        : "r"(a[0]), "r"(a[1]), "r"(a[2]), "r"(a[3]), "r"(b[0]), "r"(b[1]));
}

// ---------------------------------------------------------------------------
// fp32 -> bf16 convert for cen and W3, + reset done counters.
// ---------------------------------------------------------------------------
#define N_CEN4 (BB*CH*PP/4)   // 2359296
#define N_W34  (GG*CH*CH/4)   // 147456
__global__ __launch_bounds__(512)
void convert_kernel(const float* __restrict__ cen, const float* __restrict__ W3) {
    int i = blockIdx.x * 512 + threadIdx.x;
    if (i < BB) g_done[i] = 0;
    float4 v;
    __nv_bfloat162* dst;
    if (i < N_CEN4) {
        v = ((const float4*)cen)[i];
        dst = (__nv_bfloat162*)g_cenh + i * 2;
    } else {
        int j = i - N_CEN4;
        if (j >= N_W34) return;
        v = ((const float4*)W3)[j];
        dst = (__nv_bfloat162*)g_w3h + j * 2;
    }
    dst[0] = __floats2bfloat162_rn(v.x, v.y);
    dst[1] = __floats2bfloat162_rn(v.z, v.w);
}

// ---------------------------------------------------------------------------
// Fused kernel. bid < N_GEMM: bf16 mma GEMM tile (b-major) producing Z + ssq,
// then release-increment g_done[b]. bid >= N_GEMM: epilogue tile, acquire-spin
// on g_done[b], then out = cen + inv8*Z8 - sum inv_g(p+d)*Z_g(p+d).
// Scheduler assigns bids ascending -> all gemm CTAs scheduled before epilogue
// CTAs; epilogue of batch b overlaps gemm of later batches.
// ---------------------------------------------------------------------------
__global__ __launch_bounds__(256, 2)
void fused_kernel(const float* __restrict__ cen, float* __restrict__ out) {
    const int bid = blockIdx.x;
    const int t = threadIdx.x;

    if (bid < N_GEMM) {
        // ---------------- GEMM path ----------------
        extern __shared__ float sm[];
        const uint32_t sb = smem_u32(sm);
        const int lane = t & 31, wid = t >> 5;
        const int mwarp = wid >> 2, nwarp = wid & 3;
        const int grp = lane >> 2, tig = lane & 3;

        const int b = bid / GEMM_PER_B;
        const int r = bid % GEMM_PER_B;
        const int g = r / 144;
        const int half = (r % 144) / 72;
        const int pt = r % 72;
        const int gb = g * 4 + b;
        const int p0 = pt * 128;
        const int r0 = half * 128;

        const __nv_bfloat16* Ag = g_w3h + (size_t)g * CH * CH + (size_t)r0 * CH;
        const __nv_bfloat16* Bg = g_cenh + (size_t)b * CH * PP + p0;

        if (t < 128) sm[SSQ_OFF / 4 + t] = 0.f;

#define ISSUE_CHUNK(c, s) do {                                                  \
    const int k0 = (c) * 32;                                                    \
    _Pragma("unroll")                                                           \
    for (int q = 0; q < 2; q++) {                                               \
        int u = q * 256 + t;                                                    \
        int m = u >> 2, k4 = u & 3;                                             \
        uint32_t dst = sb + (s) * STAGE + m * ASTRIDE_B + k4 * 16;              \
        CPA16(dst, Ag + (size_t)m * CH + k0 + k4 * 8);                          \
    }                                                                           \
    _Pragma("unroll")                                                           \
    for (int q = 0; q < 2; q++) {                                               \
        int u = q * 256 + t;                                                    \
        int kr = u >> 4, c8 = u & 15;                                           \
        uint32_t dst = sb + (s) * STAGE + B_OFF + kr * BSTRIDE_B + c8 * 16;     \
        CPA16(dst, Bg + (size_t)(k0 + kr) * PP + c8 * 8);                       \
    }                                                                           \
    CPA_COMMIT();                                                               \
} while (0)

        ISSUE_CHUNK(0, 0);
        ISSUE_CHUNK(1, 1);

        float acc[4][4][4];
#pragma unroll
        for (int i = 0; i < 4; i++)
#pragma unroll
            for (int j = 0; j < 4; j++)
#pragma unroll
                for (int q = 0; q < 4; q++) acc[i][j][q] = 0.f;

        const int arow = lane & 15, ahl = lane >> 4;

        for (int c = 0; c < 8; c++) {
            const int s = c & 1;
            if (c < 7) CPA_WAIT1(); else CPA_WAIT0();
            __syncthreads();

            const uint32_t sA = sb + s * STAGE;
            const uint32_t sB = sA + B_OFF;
#pragma unroll
            for (int k16 = 0; k16 < 2; k16++) {
                uint32_t af[4][4], bf[4][2];
#pragma unroll
                for (int i = 0; i < 4; i++) {
                    uint32_t a = sA + (mwarp * 64 + i * 16 + arow) * ASTRIDE_B
                               + (ahl * 8 + k16 * 16) * 2;
                    LDSM_X4(af[i], a);
                }
#pragma unroll
                for (int jp = 0; jp < 2; jp++) {
                    uint32_t rg[4];
                    uint32_t a = sB + (k16 * 16 + arow) * BSTRIDE_B
                               + (nwarp * 32 + jp * 16 + ahl * 8) * 2;
                    LDSM_X4T(rg, a);
                    bf[jp * 2][0] = rg[0]; bf[jp * 2][1] = rg[1];
                    bf[jp * 2 + 1][0] = rg[2]; bf[jp * 2 + 1][1] = rg[3];
                }
#pragma unroll
                for (int i = 0; i < 4; i++)
#pragma unroll
                    for (int j = 0; j < 4; j++) mma16(acc[i][j], af[i], bf[j]);
            }
            if (c < 6) {
                __syncthreads();
                ISSUE_CHUNK(c + 2, s);
            }
        }

        __half* Zb = g_Zh + ((size_t)gb * CH + r0 + mwarp * 64) * PP + p0 + nwarp * 32;
        float* ssq = sm + SSQ_OFF / 4;
#pragma unroll
        for (int j = 0; j < 4; j++) {
            float s0 = 0.f, s1 = 0.f;
#pragma unroll
            for (int i = 0; i < 4; i++) {
                float* d = acc[i][j];
                s0 = fmaf(d[0], d[0], fmaf(d[2], d[2], s0));
                s1 = fmaf(d[1], d[1], fmaf(d[3], d[3], s1));
                int row = i * 16 + grp;
                int col = j * 8 + tig * 2;
                *(__half2*)(Zb + (size_t)row * PP + col)       = __floats2half2_rn(d[0], d[1]);
                *(__half2*)(Zb + (size_t)(row + 8) * PP + col) = __floats2half2_rn(d[2], d[3]);
            }
#pragma unroll
            for (int off = 4; off < 32; off <<= 1) {
                s0 += __shfl_xor_sync(0xffffffffu, s0, off);
                s1 += __shfl_xor_sync(0xffffffffu, s1, off);
            }
            if (grp == 0) {
                atomicAdd(&ssq[nwarp * 32 + j * 8 + tig * 2],     s0);
                atomicAdd(&ssq[nwarp * 32 + j * 8 + tig * 2 + 1], s1);
            }
        }
        __syncthreads();
        if (t < 128)
            g_ssq2[half][gb * PP + p0 + t] = ssq[t];
        // release: all Z + ssq stores visible before the count increment
        __threadfence();
        __syncthreads();
        if (t == 0) atomicAdd(&g_done[b], 1);
    } else {
        // ---------------- Epilogue path ----------------
        const int e = bid - N_GEMM;
        const int b = e / EPI_PER_B;
        const int r = e % EPI_PER_B;
        const int cc = (r / 36) * 32;
        const int p = (r % 36) * 256 + t;
        const int h = p / WW, w = p % WW;

        if (t == 0) {
            while (atomicAdd(&g_done[b], 0) < GEMM_PER_B) __nanosleep(200);
        }
        __syncthreads();
        __threadfence();   // acquire

        size_t off[9];
        float  sc[9];
#pragma unroll
        for (int g = 0; g < 8; g++) {
            int h2 = h + c_dy[g], w2 = w + c_dx[g];
            bool ok = (h2 >= 0) && (h2 < HH) && (w2 >= 0) && (w2 < WW);
            int p2 = ok ? h2 * WW + w2 : 0;
            int gb = g * 4 + b;
            off[g] = (size_t)gb * CH * PP + p2;
            float n = sqrtf(g_ssq2[0][gb * PP + p2] + g_ssq2[1][gb * PP + p2]);
            sc[g]  = ok ? -1.0f / fmaxf(n, 1e-12f) : 0.f;
        }
        {
            int gb = 8 * 4 + b;
            off[8] = (size_t)gb * CH * PP + p;
            float n = sqrtf(g_ssq2[0][gb * PP + p] + g_ssq2[1][gb * PP + p]);
            sc[8]  = 1.0f / fmaxf(n, 1e-12f);
        }

        const size_t cbase = (size_t)b * CH * PP + p;
#pragma unroll 4
        for (int ci = 0; ci < 32; ci++) {
            size_t cp = (size_t)(cc + ci) * PP;
            float s = cen[cbase + cp];
#pragma unroll
            for (int g = 0; g < 9; g++)
                s += sc[g] * __half2float(g_Zh[off[g] + cp]);
            out[cbase + cp] = s;
        }
    }
}

// ---------------------------------------------------------------------------
extern "C" void kernel_launch(void* const* d_in, const int* in_sizes, int n_in,
                              void* d_out, int out_size) {
    const float* cen = (const float*)d_in[0];   // (4,256,96,96)
    // d_in[1]=W1, d_in[2]=W2 dead (softmax over size-1 axis == 1)
    const float* W3  = (const float*)d_in[3];   // (9,256,256)
    float* out = (float*)d_out;

    cudaFuncSetAttribute(fused_kernel, cudaFuncAttributeMaxDynamicSharedMemorySize, SMEM_BYTES);

    convert_kernel<<<(N_CEN4 + N_W34 + 511) / 512, 512>>>(cen, W3);
    fused_kernel<<<N_CTA, 256, SMEM_BYTES>>>(cen, out);
}

// round 10
// speedup vs baseline: 1.1860x; 1.1860x over previous
#include <cuda_runtime.h>
#include <cuda_fp16.h>
#include <cuda_bf16.h>
#include <cstdint>

#define CH   256
#define HH   96
#define WW   96
#define BB   4
#define PP   (HH*WW)        // 9216
#define GG   9
#define NGB  (GG*BB)        // 36

// bf16 smem tiles: A 128 rows x 40 halves (80B stride), B 32 rows x 136 halves (272B)
#define ASTRIDE_B 80
#define BSTRIDE_B 272
#define B_OFF     10240u                 // A stage bytes = 128*80
#define STAGE     18944u                 // + B 32*272 = 8704
#define NSTAGE    4
#define SSQ_OFF   (NSTAGE*STAGE)         // 75776
#define SMEM_BYTES (SSQ_OFF + 512)       // 76288

__device__ __nv_bfloat16 g_cenh[(size_t)BB * CH * PP];
__device__ __nv_bfloat16 g_w3h[(size_t)GG * CH * CH];
__device__ __half g_Zh[(size_t)NGB * CH * PP];   // Z[gb][c][p] fp16
__device__ float  g_ssq2[2][NGB * PP];           // per-m-half partial sumsq

__constant__ int c_dy[8] = {-1, -1, -1, 0, 1, 1, 1, 0};
__constant__ int c_dx[8] = {-1,  0,  1, 1, 1, 0, -1, -1};

__device__ __forceinline__ uint32_t smem_u32(const void* p) {
    uint32_t a;
    asm("{ .reg .u64 t; cvta.to.shared.u64 t, %1; cvt.u32.u64 %0, t; }" : "=r"(a) : "l"(p));
    return a;
}
#define CPA16(dst, src) asm volatile("cp.async.cg.shared.global [%0], [%1], 16;" :: "r"(dst), "l"(src) : "memory")
#define CPA_COMMIT()    asm volatile("cp.async.commit_group;" ::: "memory")
#define CPA_WAIT(n)     asm volatile("cp.async.wait_group %0;" :: "n"(n) : "memory")

#define LDSM_X4(r, a) \
    asm volatile("ldmatrix.sync.aligned.m8n8.x4.shared.b16 {%0,%1,%2,%3}, [%4];" \
        : "=r"((r)[0]), "=r"((r)[1]), "=r"((r)[2]), "=r"((r)[3]) : "r"(a))
#define LDSM_X4T(r, a) \
    asm volatile("ldmatrix.sync.aligned.m8n8.x4.trans.shared.b16 {%0,%1,%2,%3}, [%4];" \
        : "=r"((r)[0]), "=r"((r)[1]), "=r"((r)[2]), "=r"((r)[3]) : "r"(a))

__device__ __forceinline__ void mma16(float* d, const uint32_t* a, const uint32_t* b) {
    asm volatile(
        "mma.sync.aligned.m16n8k16.row.col.f32.bf16.bf16.f32 "
        "{%0,%1,%2,%3},{%4,%5,%6,%7},{%8,%9},{%0,%1,%2,%3};"
        : "+f"(d[0]), "+f"(d[1]), "+f"(d[2]), "+f"(d[3])
        : "r"(a[0]), "r"(a[1]), "r"(a[2]), "r"(a[3]), "r"(b[0]), "r"(b[1]));
}

// ---------------------------------------------------------------------------
// fp32 -> bf16 convert for cen and W3.
// ---------------------------------------------------------------------------
#define N_CEN4 (BB*CH*PP/4)   // 2359296
#define N_W34  (GG*CH*CH/4)   // 147456
__global__ __launch_bounds__(512)
void convert_kernel(const float* __restrict__ cen, const float* __restrict__ W3) {
    int i = blockIdx.x * 512 + threadIdx.x;
    float4 v;
    __nv_bfloat162* dst;
    if (i < N_CEN4) {
        v = ((const float4*)cen)[i];
        dst = (__nv_bfloat162*)g_cenh + i * 2;
    } else {
        int j = i - N_CEN4;
        if (j >= N_W34) return;
        v = ((const float4*)W3)[j];
        dst = (__nv_bfloat162*)g_w3h + j * 2;
    }
    dst[0] = __floats2bfloat162_rn(v.x, v.y);
    dst[1] = __floats2bfloat162_rn(v.z, v.w);
}

// ---------------------------------------------------------------------------
// bf16 mma.sync GEMM (m16n8k16, ldmatrix), 4-stage cp.async pipeline.
// Z[gb] rows [r0,r0+128) = W3[g] @ cen[b][:, p0:p0+128], fp16 out,
// fused per-pixel partial sumsq. grid (72, 2, 36), 256 threads.
// ---------------------------------------------------------------------------
__global__ __launch_bounds__(256, 2)
void gemm_kernel() {
    extern __shared__ float sm[];
    const uint32_t sb = smem_u32(sm);
    const int t = threadIdx.x;
    const int lane = t & 31, wid = t >> 5;
    const int mwarp = wid >> 2, nwarp = wid & 3;
    const int grp = lane >> 2, tig = lane & 3;

    const int gb = blockIdx.z;
    const int g = gb >> 2, b = gb & 3;
    const int p0 = blockIdx.x * 128;
    const int r0 = blockIdx.y * 128;

    const __nv_bfloat16* Ag = g_w3h + (size_t)g * CH * CH + (size_t)r0 * CH;
    const __nv_bfloat16* Bg = g_cenh + (size_t)b * CH * PP + p0;

    if (t < 128) sm[SSQ_OFF / 4 + t] = 0.f;

#define ISSUE_CHUNK(c, s) do {                                                  \
    const int k0 = (c) * 32;                                                    \
    _Pragma("unroll")                                                           \
    for (int q = 0; q < 2; q++) {                                               \
        int u = q * 256 + t;                                                    \
        int m = u >> 2, k4 = u & 3;                                             \
        uint32_t dst = sb + (s) * STAGE + m * ASTRIDE_B + k4 * 16;              \
        CPA16(dst, Ag + (size_t)m * CH + k0 + k4 * 8);                          \
    }                                                                           \
    _Pragma("unroll")                                                           \
    for (int q = 0; q < 2; q++) {                                               \
        int u = q * 256 + t;                                                    \
        int kr = u >> 4, c8 = u & 15;                                           \
        uint32_t dst = sb + (s) * STAGE + B_OFF + kr * BSTRIDE_B + c8 * 16;     \
        CPA16(dst, Bg + (size_t)(k0 + kr) * PP + c8 * 8);                       \
    }                                                                           \
    CPA_COMMIT();                                                               \
} while (0)

    ISSUE_CHUNK(0, 0);
    ISSUE_CHUNK(1, 1);
    ISSUE_CHUNK(2, 2);

    float acc[4][4][4];
#pragma unroll
    for (int i = 0; i < 4; i++)
#pragma unroll
        for (int j = 0; j < 4; j++)
#pragma unroll
            for (int q = 0; q < 4; q++) acc[i][j][q] = 0.f;

    const int arow = lane & 15, ahl = lane >> 4;

#pragma unroll 1
    for (int c = 0; c < 8; c++) {
        const int s = c & 3;
        if (c < 6)      CPA_WAIT(2);
        else if (c == 6) CPA_WAIT(1);
        else             CPA_WAIT(0);
        __syncthreads();   // chunk c arrived; all warps done reading stage (c-1)&3

        if (c + 3 < 8) ISSUE_CHUNK(c + 3, (c + 3) & 3);

        const uint32_t sA = sb + s * STAGE;
        const uint32_t sB = sA + B_OFF;
#pragma unroll
        for (int k16 = 0; k16 < 2; k16++) {
            uint32_t af[4][4], bf[4][2];
#pragma unroll
            for (int i = 0; i < 4; i++) {
                uint32_t a = sA + (mwarp * 64 + i * 16 + arow) * ASTRIDE_B
                           + (ahl * 8 + k16 * 16) * 2;
                LDSM_X4(af[i], a);
            }
#pragma unroll
            for (int jp = 0; jp < 2; jp++) {
                uint32_t rg[4];
                uint32_t a = sB + (k16 * 16 + arow) * BSTRIDE_B
                           + (nwarp * 32 + jp * 16 + ahl * 8) * 2;
                LDSM_X4T(rg, a);
                bf[jp * 2][0] = rg[0]; bf[jp * 2][1] = rg[1];
                bf[jp * 2 + 1][0] = rg[2]; bf[jp * 2 + 1][1] = rg[3];
            }
#pragma unroll
            for (int i = 0; i < 4; i++)
#pragma unroll
                for (int j = 0; j < 4; j++) mma16(acc[i][j], af[i], bf[j]);
        }
    }

    // Store Z (fp16) + fused per-pixel sumsq.
    __half* Zb = g_Zh + ((size_t)gb * CH + r0 + mwarp * 64) * PP + p0 + nwarp * 32;
    float* ssq = sm + SSQ_OFF / 4;
#pragma unroll
    for (int j = 0; j < 4; j++) {
        float s0 = 0.f, s1 = 0.f;
#pragma unroll
        for (int i = 0; i < 4; i++) {
            float* d = acc[i][j];
            s0 = fmaf(d[0], d[0], fmaf(d[2], d[2], s0));
            s1 = fmaf(d[1], d[1], fmaf(d[3], d[3], s1));
            int row = i * 16 + grp;
            int col = j * 8 + tig * 2;
            *(__half2*)(Zb + (size_t)row * PP + col)       = __floats2half2_rn(d[0], d[1]);
            *(__half2*)(Zb + (size_t)(row + 8) * PP + col) = __floats2half2_rn(d[2], d[3]);
        }
#pragma unroll
        for (int off = 4; off < 32; off <<= 1) {
            s0 += __shfl_xor_sync(0xffffffffu, s0, off);
            s1 += __shfl_xor_sync(0xffffffffu, s1, off);
        }
        if (grp == 0) {
            atomicAdd(&ssq[nwarp * 32 + j * 8 + tig * 2],     s0);
            atomicAdd(&ssq[nwarp * 32 + j * 8 + tig * 2 + 1], s1);
        }
    }
    __syncthreads();
    if (t < 128)
        g_ssq2[blockIdx.y][gb * PP + p0 + t] = ssq[t];
}

// ---------------------------------------------------------------------------
// Epilogue: out = cen + inv8*Z8 - sum_{g<8} inv_g(p+d)*Z_g(p+d)
// 4-channel batched loads for deep MLP. grid (36, 8, 4), 256 threads.
// ---------------------------------------------------------------------------
__global__ __launch_bounds__(256)
void epilogue_kernel(const float* __restrict__ cen, float* __restrict__ out) {
    const int t  = threadIdx.x;
    const int cc = blockIdx.y * 32;
    const int b  = blockIdx.z;
    const int p  = blockIdx.x * 256 + t;
    const int h  = p / WW, w = p % WW;

    size_t off[9];
    float  sc[9];
#pragma unroll
    for (int g = 0; g < 8; g++) {
        int h2 = h + c_dy[g], w2 = w + c_dx[g];
        bool ok = (h2 >= 0) && (h2 < HH) && (w2 >= 0) && (w2 < WW);
        int p2 = ok ? h2 * WW + w2 : 0;
        int gb = g * 4 + b;
        off[g] = (size_t)gb * CH * PP + p2;
        float n = sqrtf(g_ssq2[0][gb * PP + p2] + g_ssq2[1][gb * PP + p2]);
        sc[g]  = ok ? -1.0f / fmaxf(n, 1e-12f) : 0.f;
    }
    {
        int gb = 8 * 4 + b;
        off[8] = (size_t)gb * CH * PP + p;
        float n = sqrtf(g_ssq2[0][gb * PP + p] + g_ssq2[1][gb * PP + p]);
        sc[8]  = 1.0f / fmaxf(n, 1e-12f);
    }

    const size_t cbase = (size_t)b * CH * PP + p;
#pragma unroll 1
    for (int s4 = 0; s4 < 8; s4++) {
        float  cq[4];
        __half zq[4][9];
#pragma unroll
        for (int q = 0; q < 4; q++) {
            size_t cp = (size_t)(cc + s4 * 4 + q) * PP;
            cq[q] = cen[cbase + cp];
#pragma unroll
            for (int g = 0; g < 9; g++)
                zq[q][g] = g_Zh[off[g] + cp];
        }
#pragma unroll
        for (int q = 0; q < 4; q++) {
            float s = cq[q];
#pragma unroll
            for (int g = 0; g < 9; g++)
                s += sc[g] * __half2float(zq[q][g]);
            out[cbase + (size_t)(cc + s4 * 4 + q) * PP] = s;
        }
    }
}

// ---------------------------------------------------------------------------
extern "C" void kernel_launch(void* const* d_in, const int* in_sizes, int n_in,
                              void* d_out, int out_size) {
    const float* cen = (const float*)d_in[0];   // (4,256,96,96)
    // d_in[1]=W1, d_in[2]=W2 dead (softmax over size-1 axis == 1)
    const float* W3  = (const float*)d_in[3];   // (9,256,256)
    float* out = (float*)d_out;

    cudaFuncSetAttribute(gemm_kernel, cudaFuncAttributeMaxDynamicSharedMemorySize, SMEM_BYTES);

    convert_kernel<<<(N_CEN4 + N_W34 + 511) / 512, 512>>>(cen, W3);
    gemm_kernel<<<dim3(PP / 128, 2, NGB), 256, SMEM_BYTES>>>();
    epilogue_kernel<<<dim3(PP / 256, CH / 32, BB), 256>>>(cen, out);
}

// round 11
// speedup vs baseline: 1.2775x; 1.0772x over previous
#include <cuda_runtime.h>
#include <cuda_fp16.h>
#include <cuda_bf16.h>
#include <cstdint>

#define CH   256
#define HH   96
#define WW   96
#define BB   4
#define PP   (HH*WW)        // 9216
#define GG   9
#define NGB  (GG*BB)        // 36

// bf16 smem tiles: A 128 rows x 40 halves (80B stride), B 32 rows x 136 halves (272B)
#define ASTRIDE_B 80
#define BSTRIDE_B 272
#define B_OFF     10240u                 // A stage bytes = 128*80
#define STAGE     18944u                 // + B 32*272 = 8704
#define NSTAGE    4
#define SSQ_OFF   (NSTAGE*STAGE)         // 75776
#define SMEM_BYTES (SSQ_OFF + 512)       // 76288
#define ZST       136                    // Z smem tile row stride (halves)

__device__ __nv_bfloat16 g_cenh[(size_t)BB * CH * PP];
__device__ __nv_bfloat16 g_w3h[(size_t)GG * CH * CH];
__device__ __half g_Zh[(size_t)NGB * CH * PP];   // Z[gb][c][p] fp16
__device__ float  g_ssq2[2][NGB * PP];           // per-m-half partial sumsq

__constant__ int c_dy[8] = {-1, -1, -1, 0, 1, 1, 1, 0};
__constant__ int c_dx[8] = {-1,  0,  1, 1, 1, 0, -1, -1};

__device__ __forceinline__ uint32_t smem_u32(const void* p) {
    uint32_t a;
    asm("{ .reg .u64 t; cvta.to.shared.u64 t, %1; cvt.u32.u64 %0, t; }" : "=r"(a) : "l"(p));
    return a;
}
#define CPA16(dst, src) asm volatile("cp.async.cg.shared.global [%0], [%1], 16;" :: "r"(dst), "l"(src) : "memory")
#define CPA_COMMIT()    asm volatile("cp.async.commit_group;" ::: "memory")
#define CPA_WAIT(n)     asm volatile("cp.async.wait_group %0;" :: "n"(n) : "memory")

#define LDSM_X4(r, a) \
    asm volatile("ldmatrix.sync.aligned.m8n8.x4.shared.b16 {%0,%1,%2,%3}, [%4];" \
        : "=r"((r)[0]), "=r"((r)[1]), "=r"((r)[2]), "=r"((r)[3]) : "r"(a))
#define LDSM_X4T(r, a) \
    asm volatile("ldmatrix.sync.aligned.m8n8.x4.trans.shared.b16 {%0,%1,%2,%3}, [%4];" \
        : "=r"((r)[0]), "=r"((r)[1]), "=r"((r)[2]), "=r"((r)[3]) : "r"(a))

__device__ __forceinline__ void mma16(float* d, const uint32_t* a, const uint32_t* b) {
    asm volatile(
        "mma.sync.aligned.m16n8k16.row.col.f32.bf16.bf16.f32 "
        "{%0,%1,%2,%3},{%4,%5,%6,%7},{%8,%9},{%0,%1,%2,%3};"
        : "+f"(d[0]), "+f"(d[1]), "+f"(d[2]), "+f"(d[3])
        : "r"(a[0]), "r"(a[1]), "r"(a[2]), "r"(a[3]), "r"(b[0]), "r"(b[1]));
}

// ---------------------------------------------------------------------------
// fp32 -> bf16 convert for cen and W3.
// ---------------------------------------------------------------------------
#define N_CEN4 (BB*CH*PP/4)   // 2359296
#define N_W34  (GG*CH*CH/4)   // 147456
__global__ __launch_bounds__(512)
void convert_kernel(const float* __restrict__ cen, const float* __restrict__ W3) {
    int i = blockIdx.x * 512 + threadIdx.x;
    float4 v;
    __nv_bfloat162* dst;
    if (i < N_CEN4) {
        v = ((const float4*)cen)[i];
        dst = (__nv_bfloat162*)g_cenh + i * 2;
    } else {
        int j = i - N_CEN4;
        if (j >= N_W34) return;
        v = ((const float4*)W3)[j];
        dst = (__nv_bfloat162*)g_w3h + j * 2;
    }
    dst[0] = __floats2bfloat162_rn(v.x, v.y);
    dst[1] = __floats2bfloat162_rn(v.z, v.w);
}

// ---------------------------------------------------------------------------
// bf16 mma.sync GEMM (m16n8k16, ldmatrix), 4-stage cp.async pipeline,
// smem-staged coalesced Z store. grid (72, 2, 36), 256 threads.
// ---------------------------------------------------------------------------
__global__ __launch_bounds__(256, 2)
void gemm_kernel() {
    extern __shared__ float sm[];
    const uint32_t sb = smem_u32(sm);
    const int t = threadIdx.x;
    const int lane = t & 31, wid = t >> 5;
    const int mwarp = wid >> 2, nwarp = wid & 3;
    const int grp = lane >> 2, tig = lane & 3;

    const int gb = blockIdx.z;
    const int g = gb >> 2, b = gb & 3;
    const int p0 = blockIdx.x * 128;
    const int r0 = blockIdx.y * 128;

    const __nv_bfloat16* Ag = g_w3h + (size_t)g * CH * CH + (size_t)r0 * CH;
    const __nv_bfloat16* Bg = g_cenh + (size_t)b * CH * PP + p0;

    if (t < 128) sm[SSQ_OFF / 4 + t] = 0.f;

#define ISSUE_CHUNK(c, s) do {                                                  \
    const int k0 = (c) * 32;                                                    \
    _Pragma("unroll")                                                           \
    for (int q = 0; q < 2; q++) {                                               \
        int u = q * 256 + t;                                                    \
        int m = u >> 2, k4 = u & 3;                                             \
        uint32_t dst = sb + (s) * STAGE + m * ASTRIDE_B + k4 * 16;              \
        CPA16(dst, Ag + (size_t)m * CH + k0 + k4 * 8);                          \
    }                                                                           \
    _Pragma("unroll")                                                           \
    for (int q = 0; q < 2; q++) {                                               \
        int u = q * 256 + t;                                                    \
        int kr = u >> 4, c8 = u & 15;                                           \
        uint32_t dst = sb + (s) * STAGE + B_OFF + kr * BSTRIDE_B + c8 * 16;     \
        CPA16(dst, Bg + (size_t)(k0 + kr) * PP + c8 * 8);                       \
    }                                                                           \
    CPA_COMMIT();                                                               \
} while (0)

    ISSUE_CHUNK(0, 0);
    ISSUE_CHUNK(1, 1);
    ISSUE_CHUNK(2, 2);

    float acc[4][4][4];
#pragma unroll
    for (int i = 0; i < 4; i++)
#pragma unroll
        for (int j = 0; j < 4; j++)
#pragma unroll
            for (int q = 0; q < 4; q++) acc[i][j][q] = 0.f;

    const int arow = lane & 15, ahl = lane >> 4;

#pragma unroll 1
    for (int c = 0; c < 8; c++) {
        const int s = c & 3;
        if (c < 6)      CPA_WAIT(2);
        else if (c == 6) CPA_WAIT(1);
        else             CPA_WAIT(0);
        __syncthreads();

        if (c + 3 < 8) ISSUE_CHUNK(c + 3, (c + 3) & 3);

        const uint32_t sA = sb + s * STAGE;
        const uint32_t sB = sA + B_OFF;
#pragma unroll
        for (int k16 = 0; k16 < 2; k16++) {
            uint32_t af[4][4], bf[4][2];
#pragma unroll
            for (int i = 0; i < 4; i++) {
                uint32_t a = sA + (mwarp * 64 + i * 16 + arow) * ASTRIDE_B
                           + (ahl * 8 + k16 * 16) * 2;
                LDSM_X4(af[i], a);
            }
#pragma unroll
            for (int jp = 0; jp < 2; jp++) {
                uint32_t rg[4];
                uint32_t a = sB + (k16 * 16 + arow) * BSTRIDE_B
                           + (nwarp * 32 + jp * 16 + ahl * 8) * 2;
                LDSM_X4T(rg, a);
                bf[jp * 2][0] = rg[0]; bf[jp * 2][1] = rg[1];
                bf[jp * 2 + 1][0] = rg[2]; bf[jp * 2 + 1][1] = rg[3];
            }
#pragma unroll
            for (int i = 0; i < 4; i++)
#pragma unroll
                for (int j = 0; j < 4; j++) mma16(acc[i][j], af[i], bf[j]);
        }
    }

    // Frags -> smem Z tile (conflict-free scatter) + fused per-pixel sumsq.
    __syncthreads();   // pipeline stages fully consumed; reuse as Z tile
    __half* zs = (__half*)sm;     // [128 rows][ZST halves]
    float* ssq = sm + SSQ_OFF / 4;
#pragma unroll
    for (int j = 0; j < 4; j++) {
        float s0 = 0.f, s1 = 0.f;
#pragma unroll
        for (int i = 0; i < 4; i++) {
            float* d = acc[i][j];
            s0 = fmaf(d[0], d[0], fmaf(d[2], d[2], s0));
            s1 = fmaf(d[1], d[1], fmaf(d[3], d[3], s1));
            int row = mwarp * 64 + i * 16 + grp;
            int col = nwarp * 32 + j * 8 + tig * 2;
            *(__half2*)(zs + (size_t)row * ZST + col)       = __floats2half2_rn(d[0], d[1]);
            *(__half2*)(zs + (size_t)(row + 8) * ZST + col) = __floats2half2_rn(d[2], d[3]);
        }
#pragma unroll
        for (int off = 4; off < 32; off <<= 1) {
            s0 += __shfl_xor_sync(0xffffffffu, s0, off);
            s1 += __shfl_xor_sync(0xffffffffu, s1, off);
        }
        if (grp == 0) {
            atomicAdd(&ssq[nwarp * 32 + j * 8 + tig * 2],     s0);
            atomicAdd(&ssq[nwarp * 32 + j * 8 + tig * 2 + 1], s1);
        }
    }
    __syncthreads();

    // Coalesced Z store: 8 passes x 16 rows, 16 threads per row (256B/row).
    __half* Zt = g_Zh + ((size_t)gb * CH + r0) * PP + p0;
#pragma unroll
    for (int pass = 0; pass < 8; pass++) {
        int row = pass * 16 + (t >> 4);
        int co  = (t & 15) * 8;
        uint4 v = *(const uint4*)(zs + (size_t)row * ZST + co);
        *(uint4*)(Zt + (size_t)row * PP + co) = v;
    }
    if (t < 128)
        g_ssq2[blockIdx.y][gb * PP + p0 + t] = ssq[t];
}

// ---------------------------------------------------------------------------
// Epilogue: out = cen + inv8*Z8 - sum_{g<8} inv_g(p+d)*Z_g(p+d)
// 4-channel batched loads for deep MLP. grid (36, 8, 4), 256 threads.
// ---------------------------------------------------------------------------
__global__ __launch_bounds__(256)
void epilogue_kernel(const float* __restrict__ cen, float* __restrict__ out) {
    const int t  = threadIdx.x;
    const int cc = blockIdx.y * 32;
    const int b  = blockIdx.z;
    const int p  = blockIdx.x * 256 + t;
    const int h  = p / WW, w = p % WW;

    size_t off[9];
    float  sc[9];
#pragma unroll
    for (int g = 0; g < 8; g++) {
        int h2 = h + c_dy[g], w2 = w + c_dx[g];
        bool ok = (h2 >= 0) && (h2 < HH) && (w2 >= 0) && (w2 < WW);
        int p2 = ok ? h2 * WW + w2 : 0;
        int gb = g * 4 + b;
        off[g] = (size_t)gb * CH * PP + p2;
        float n = sqrtf(g_ssq2[0][gb * PP + p2] + g_ssq2[1][gb * PP + p2]);
        sc[g]  = ok ? -1.0f / fmaxf(n, 1e-12f) : 0.f;
    }
    {
        int gb = 8 * 4 + b;
        off[8] = (size_t)gb * CH * PP + p;
        float n = sqrtf(g_ssq2[0][gb * PP + p] + g_ssq2[1][gb * PP + p]);
        sc[8]  = 1.0f / fmaxf(n, 1e-12f);
    }

    const size_t cbase = (size_t)b * CH * PP + p;
#pragma unroll 1
    for (int s4 = 0; s4 < 8; s4++) {
        float  cq[4];
        __half zq[4][9];
#pragma unroll
        for (int q = 0; q < 4; q++) {
            size_t cp = (size_t)(cc + s4 * 4 + q) * PP;
            cq[q] = cen[cbase + cp];
#pragma unroll
            for (int g = 0; g < 9; g++)
                zq[q][g] = g_Zh[off[g] + cp];
        }
#pragma unroll
        for (int q = 0; q < 4; q++) {
            float s = cq[q];
#pragma unroll
            for (int g = 0; g < 9; g++)
                s += sc[g] * __half2float(zq[q][g]);
            out[cbase + (size_t)(cc + s4 * 4 + q) * PP] = s;
        }
    }
}

// ---------------------------------------------------------------------------
extern "C" void kernel_launch(void* const* d_in, const int* in_sizes, int n_in,
                              void* d_out, int out_size) {
    const float* cen = (const float*)d_in[0];   // (4,256,96,96)
    // d_in[1]=W1, d_in[2]=W2 dead (softmax over size-1 axis == 1)
    const float* W3  = (const float*)d_in[3];   // (9,256,256)
    float* out = (float*)d_out;

    cudaFuncSetAttribute(gemm_kernel, cudaFuncAttributeMaxDynamicSharedMemorySize, SMEM_BYTES);

    convert_kernel<<<(N_CEN4 + N_W34 + 511) / 512, 512>>>(cen, W3);
    gemm_kernel<<<dim3(PP / 128, 2, NGB), 256, SMEM_BYTES>>>();
    epilogue_kernel<<<dim3(PP / 256, CH / 32, BB), 256>>>(cen, out);
}

// round 16
// speedup vs baseline: 1.4193x; 1.1110x over previous
#include <cuda_runtime.h>
#include <cuda_fp16.h>
#include <cuda_bf16.h>
#include <cstdint>

#define CH   256
#define HH   96
#define WW   96
#define BB   4
#define PP   (HH*WW)        // 9216
#define GG   9
#define NGB  (GG*BB)        // 36

// bf16 smem tiles, K-chunk = 64:
//   A 128 rows x 144B stride (72 halves; 64 used) = 18432 B  (16B-aligned rows!)
//   B 64 rows x 272B stride (136 halves)          = 17408 B
#define ASTRIDE_B 144
#define BSTRIDE_B 272
#define B_OFF     18432u
#define STAGE     35840u
#define NSTAGE    3
#define SSQ_OFF   (NSTAGE*STAGE)         // 107520
#define SMEM_BYTES (SSQ_OFF + 512)       // 108032
#define ZST       136                    // Z smem tile row stride (halves)

__device__ __nv_bfloat16 g_cenh[(size_t)BB * CH * PP];
__device__ __nv_bfloat16 g_w3h[(size_t)GG * CH * CH];
__device__ __half g_Zh[(size_t)NGB * CH * PP];   // Z[gb][c][p] fp16
__device__ float  g_ssq2[2][NGB * PP];           // per-m-half partial sumsq

__constant__ int c_dy[8] = {-1, -1, -1, 0, 1, 1, 1, 0};
__constant__ int c_dx[8] = {-1,  0,  1, 1, 1, 0, -1, -1};

__device__ __forceinline__ uint32_t smem_u32(const void* p) {
    uint32_t a;
    asm("{ .reg .u64 t; cvta.to.shared.u64 t, %1; cvt.u32.u64 %0, t; }" : "=r"(a) : "l"(p));
    return a;
}
#define CPA16(dst, src) asm volatile("cp.async.cg.shared.global [%0], [%1], 16;" :: "r"(dst), "l"(src) : "memory")
#define CPA_COMMIT()    asm volatile("cp.async.commit_group;" ::: "memory")
#define CPA_WAIT(n)     asm volatile("cp.async.wait_group %0;" :: "n"(n) : "memory")

#define LDSM_X4(r, a) \
    asm volatile("ldmatrix.sync.aligned.m8n8.x4.shared.b16 {%0,%1,%2,%3}, [%4];" \
        : "=r"((r)[0]), "=r"((r)[1]), "=r"((r)[2]), "=r"((r)[3]) : "r"(a))
#define LDSM_X4T(r, a) \
    asm volatile("ldmatrix.sync.aligned.m8n8.x4.trans.shared.b16 {%0,%1,%2,%3}, [%4];" \
        : "=r"((r)[0]), "=r"((r)[1]), "=r"((r)[2]), "=r"((r)[3]) : "r"(a))

__device__ __forceinline__ void mma16(float* d, const uint32_t* a, const uint32_t* b) {
    asm volatile(
        "mma.sync.aligned.m16n8k16.row.col.f32.bf16.bf16.f32 "
        "{%0,%1,%2,%3},{%4,%5,%6,%7},{%8,%9},{%0,%1,%2,%3};"
        : "+f"(d[0]), "+f"(d[1]), "+f"(d[2]), "+f"(d[3])
        : "r"(a[0]), "r"(a[1]), "r"(a[2]), "r"(a[3]), "r"(b[0]), "r"(b[1]));
}

// ---------------------------------------------------------------------------
// fp32 -> bf16 convert for cen and W3.
// ---------------------------------------------------------------------------
#define N_CEN4 (BB*CH*PP/4)   // 2359296
#define N_W34  (GG*CH*CH/4)   // 147456
__global__ __launch_bounds__(512)
void convert_kernel(const float* __restrict__ cen, const float* __restrict__ W3) {
    int i = blockIdx.x * 512 + threadIdx.x;
    float4 v;
    __nv_bfloat162* dst;
    if (i < N_CEN4) {
        v = ((const float4*)cen)[i];
        dst = (__nv_bfloat162*)g_cenh + i * 2;
    } else {
        int j = i - N_CEN4;
        if (j >= N_W34) return;
        v = ((const float4*)W3)[j];
        dst = (__nv_bfloat162*)g_w3h + j * 2;
    }
    dst[0] = __floats2bfloat162_rn(v.x, v.y);
    dst[1] = __floats2bfloat162_rn(v.z, v.w);
}

// ---------------------------------------------------------------------------
// bf16 mma.sync GEMM (m16n8k16, ldmatrix), K-chunk 64, 3-stage cp.async,
// smem-staged coalesced Z store. grid (72, 2, 36), 256 threads.
// ---------------------------------------------------------------------------
__global__ __launch_bounds__(256, 2)
void gemm_kernel() {
    extern __shared__ float sm[];
    const uint32_t sb = smem_u32(sm);
    const int t = threadIdx.x;
    const int lane = t & 31, wid = t >> 5;
    const int mwarp = wid >> 2, nwarp = wid & 3;
    const int grp = lane >> 2, tig = lane & 3;

    const int gb = blockIdx.z;
    const int g = gb >> 2, b = gb & 3;
    const int p0 = blockIdx.x * 128;
    const int r0 = blockIdx.y * 128;

    const __nv_bfloat16* Ag = g_w3h + (size_t)g * CH * CH + (size_t)r0 * CH;
    const __nv_bfloat16* Bg = g_cenh + (size_t)b * CH * PP + p0;

    if (t < 128) sm[SSQ_OFF / 4 + t] = 0.f;

#define ISSUE_CHUNK(c, s) do {                                                  \
    const int k0 = (c) * 64;                                                    \
    _Pragma("unroll")                                                           \
    for (int q = 0; q < 4; q++) {                                               \
        int u = q * 256 + t;                                                    \
        int m = u >> 3, k8 = u & 7;                                             \
        uint32_t dst = sb + (s) * STAGE + m * ASTRIDE_B + k8 * 16;              \
        CPA16(dst, Ag + (size_t)m * CH + k0 + k8 * 8);                          \
    }                                                                           \
    _Pragma("unroll")                                                           \
    for (int q = 0; q < 4; q++) {                                               \
        int u = q * 256 + t;                                                    \
        int kr = u >> 4, c8 = u & 15;                                           \
        uint32_t dst = sb + (s) * STAGE + B_OFF + kr * BSTRIDE_B + c8 * 16;     \
        CPA16(dst, Bg + (size_t)(k0 + kr) * PP + c8 * 8);                       \
    }                                                                           \
    CPA_COMMIT();                                                               \
} while (0)

    ISSUE_CHUNK(0, 0);
    ISSUE_CHUNK(1, 1);

    float acc[4][4][4];
#pragma unroll
    for (int i = 0; i < 4; i++)
#pragma unroll
        for (int j = 0; j < 4; j++)
#pragma unroll
            for (int q = 0; q < 4; q++) acc[i][j][q] = 0.f;

    const int arow = lane & 15, ahl = lane >> 4;

#pragma unroll 1
    for (int c = 0; c < 4; c++) {
        const int s = c % 3;
        if (c < 3) CPA_WAIT(1); else CPA_WAIT(0);
        __syncthreads();   // chunk c arrived; stage (c+2)%3 fully consumed

        if (c + 2 < 4) ISSUE_CHUNK(c + 2, (c + 2) % 3);

        const uint32_t sA = sb + s * STAGE;
        const uint32_t sB = sA + B_OFF;
#pragma unroll
        for (int k16 = 0; k16 < 4; k16++) {
            uint32_t af[4][4], bf[4][2];
#pragma unroll
            for (int i = 0; i < 4; i++) {
                uint32_t a = sA + (mwarp * 64 + i * 16 + arow) * ASTRIDE_B
                           + (ahl * 8 + k16 * 16) * 2;
                LDSM_X4(af[i], a);
            }
#pragma unroll
            for (int jp = 0; jp < 2; jp++) {
                uint32_t rg[4];
                uint32_t a = sB + (k16 * 16 + arow) * BSTRIDE_B
                           + (nwarp * 32 + jp * 16 + ahl * 8) * 2;
                LDSM_X4T(rg, a);
                bf[jp * 2][0] = rg[0]; bf[jp * 2][1] = rg[1];
                bf[jp * 2 + 1][0] = rg[2]; bf[jp * 2 + 1][1] = rg[3];
            }
#pragma unroll
            for (int i = 0; i < 4; i++)
#pragma unroll
                for (int j = 0; j < 4; j++) mma16(acc[i][j], af[i], bf[j]);
        }
    }

    // Frags -> smem Z tile (conflict-free scatter) + fused per-pixel sumsq.
    __syncthreads();   // pipeline stages fully consumed; reuse as Z tile
    __half* zs = (__half*)sm;     // [128 rows][ZST halves]
    float* ssq = sm + SSQ_OFF / 4;
#pragma unroll
    for (int j = 0; j < 4; j++) {
        float s0 = 0.f, s1 = 0.f;
#pragma unroll
        for (int i = 0; i < 4; i++) {
            float* d = acc[i][j];
            s0 = fmaf(d[0], d[0], fmaf(d[2], d[2], s0));
            s1 = fmaf(d[1], d[1], fmaf(d[3], d[3], s1));
            int row = mwarp * 64 + i * 16 + grp;
            int col = nwarp * 32 + j * 8 + tig * 2;
            *(__half2*)(zs + (size_t)row * ZST + col)       = __floats2half2_rn(d[0], d[1]);
            *(__half2*)(zs + (size_t)(row + 8) * ZST + col) = __floats2half2_rn(d[2], d[3]);
        }
#pragma unroll
        for (int off = 4; off < 32; off <<= 1) {
            s0 += __shfl_xor_sync(0xffffffffu, s0, off);
            s1 += __shfl_xor_sync(0xffffffffu, s1, off);
        }
        if (grp == 0) {
            atomicAdd(&ssq[nwarp * 32 + j * 8 + tig * 2],     s0);
            atomicAdd(&ssq[nwarp * 32 + j * 8 + tig * 2 + 1], s1);
        }
    }
    __syncthreads();

    // Coalesced Z store: 8 passes x 16 rows, 16 threads per row (256B/row).
    __half* Zt = g_Zh + ((size_t)gb * CH + r0) * PP + p0;
#pragma unroll
    for (int pass = 0; pass < 8; pass++) {
        int row = pass * 16 + (t >> 4);
        int co  = (t & 15) * 8;
        uint4 v = *(const uint4*)(zs + (size_t)row * ZST + co);
        *(uint4*)(Zt + (size_t)row * PP + co) = v;
    }
    if (t < 128)
        g_ssq2[blockIdx.y][gb * PP + p0 + t] = ssq[t];
}

// ---------------------------------------------------------------------------
// Epilogue: out = cen + inv8*Z8 - sum_{g<8} inv_g(p+d)*Z_g(p+d)
// 4-channel batched loads for deep MLP. grid (36, 8, 4), 256 threads.
// ---------------------------------------------------------------------------
__global__ __launch_bounds__(256)
void epilogue_kernel(const float* __restrict__ cen, float* __restrict__ out) {
    const int t  = threadIdx.x;
    const int cc = blockIdx.y * 32;
    const int b  = blockIdx.z;
    const int p  = blockIdx.x * 256 + t;
    const int h  = p / WW, w = p % WW;

    size_t off[9];
    float  sc[9];
#pragma unroll
    for (int g = 0; g < 8; g++) {
        int h2 = h + c_dy[g], w2 = w + c_dx[g];
        bool ok = (h2 >= 0) && (h2 < HH) && (w2 >= 0) && (w2 < WW);
        int p2 = ok ? h2 * WW + w2 : 0;
        int gb = g * 4 + b;
        off[g] = (size_t)gb * CH * PP + p2;
        float n = sqrtf(g_ssq2[0][gb * PP + p2] + g_ssq2[1][gb * PP + p2]);
        sc[g]  = ok ? -1.0f / fmaxf(n, 1e-12f) : 0.f;
    }
    {
        int gb = 8 * 4 + b;
        off[8] = (size_t)gb * CH * PP + p;
        float n = sqrtf(g_ssq2[0][gb * PP + p] + g_ssq2[1][gb * PP + p]);
        sc[8]  = 1.0f / fmaxf(n, 1e-12f);
    }

    const size_t cbase = (size_t)b * CH * PP + p;
#pragma unroll 1
    for (int s4 = 0; s4 < 8; s4++) {
        float  cq[4];
        __half zq[4][9];
#pragma unroll
        for (int q = 0; q < 4; q++) {
            size_t cp = (size_t)(cc + s4 * 4 + q) * PP;
            cq[q] = cen[cbase + cp];
#pragma unroll
            for (int g = 0; g < 9; g++)
                zq[q][g] = g_Zh[off[g] + cp];
        }
#pragma unroll
        for (int q = 0; q < 4; q++) {
            float s = cq[q];
#pragma unroll
            for (int g = 0; g < 9; g++)
                s += sc[g] * __half2float(zq[q][g]);
            out[cbase + (size_t)(cc + s4 * 4 + q) * PP] = s;
        }
    }
}

// ---------------------------------------------------------------------------
extern "C" void kernel_launch(void* const* d_in, const int* in_sizes, int n_in,
                              void* d_out, int out_size) {
    const float* cen = (const float*)d_in[0];   // (4,256,96,96)
    // d_in[1]=W1, d_in[2]=W2 dead (softmax over size-1 axis == 1)
    const float* W3  = (const float*)d_in[3];   // (9,256,256)
    float* out = (float*)d_out;

    cudaFuncSetAttribute(gemm_kernel, cudaFuncAttributeMaxDynamicSharedMemorySize, SMEM_BYTES);

    convert_kernel<<<(N_CEN4 + N_W34 + 511) / 512, 512>>>(cen, W3);
    gemm_kernel<<<dim3(PP / 128, 2, NGB), 256, SMEM_BYTES>>>();
    epilogue_kernel<<<dim3(PP / 256, CH / 32, BB), 256>>>(cen, out);
}